// round 1
// baseline (speedup 1.0000x reference)
#include <cuda_runtime.h>
#include <cstdint>

// Problem constants
#define Bn    512
#define Hh    50
#define Tt    1024
#define STATE 13
#define CTRL  4
#define LAT   128
#define HID   256

// ---------------- scratch (no allocations allowed) ----------------
__device__ float g_h[Bn * HID];                       // 0.5 MB
__device__ float g_A[(size_t)Bn * LAT * LAT];         // 32 MB   A_dt = I + delta_A
__device__ float g_Bm[Bn * LAT * CTRL];               // 1 MB
__device__ float g_z[(size_t)Bn * (Tt + 1) * LAT];    // 268.8 MB z trajectory

// ---------------- f32x2 packed FMA helpers ----------------
__device__ __forceinline__ unsigned long long pack2(float x, float y) {
    unsigned long long r;
    asm("mov.b64 %0, {%1, %2};" : "=l"(r) : "f"(x), "f"(y));
    return r;
}
__device__ __forceinline__ void unpack2(unsigned long long v, float& x, float& y) {
    asm("mov.b64 {%0, %1}, %2;" : "=f"(x), "=f"(y) : "l"(v));
}
__device__ __forceinline__ void ffma2(unsigned long long& d, unsigned long long a,
                                      unsigned long long b) {
    asm("fma.rn.f32x2 %0, %1, %2, %3;" : "=l"(d) : "l"(a), "l"(b), "l"(d));
}

// ---------------- kernel 1: context mean + tanh MLP ----------------
__global__ void k_ctxt(const float* __restrict__ xh, const float* __restrict__ uh,
                       const float* __restrict__ Wc, const float* __restrict__ bc) {
    int b = blockIdx.x;
    int tid = threadIdx.x;
    __shared__ float m[STATE + CTRL];

    if (tid < STATE + CTRL) {
        float s = 0.f;
        if (tid < STATE) {
            const float* p = xh + (size_t)b * Hh * STATE + tid;
            for (int r = 0; r < Hh; r++) s += p[r * STATE];
        } else {
            const float* p = uh + (size_t)b * Hh * CTRL + (tid - STATE);
            for (int r = 0; r < Hh; r++) s += p[r * CTRL];
        }
        m[tid] = s * (1.0f / (float)Hh);
    }
    __syncthreads();

    float acc = bc[tid];
#pragma unroll
    for (int c = 0; c < STATE + CTRL; c++) acc += m[c] * Wc[c * HID + tid];
    g_h[b * HID + tid] = tanhf(acc);
}

// ---------------- kernel 2: A = I + h @ W_A + b_A  (tiled GEMM) ----------------
#define BM 32
#define BN 128
#define BK 32
__global__ void k_gemmA(const float* __restrict__ WA, const float* __restrict__ bA) {
    __shared__ float hs[BK][BM + 1];
    __shared__ float Ws[BK][BN];
    int tid = threadIdx.x;
    int c0 = blockIdx.x * BN;
    int b0 = blockIdx.y * BM;
    int ry = tid >> 5;   // 0..7   (4 batch rows each)
    int cx = tid & 31;   // 0..31  (4 cols each)

    float acc[4][4];
#pragma unroll
    for (int i = 0; i < 4; i++)
#pragma unroll
        for (int j = 0; j < 4; j++) acc[i][j] = 0.f;

    for (int k0 = 0; k0 < HID; k0 += BK) {
        for (int idx = tid; idx < BM * BK; idx += 256) {
            int bb = idx >> 5, kk = idx & 31;
            hs[kk][bb] = g_h[(b0 + bb) * HID + k0 + kk];
        }
        for (int idx = tid; idx < BK * BN; idx += 256) {
            int kk = idx >> 7, cc = idx & 127;
            Ws[kk][cc] = WA[(size_t)(k0 + kk) * (LAT * LAT) + c0 + cc];
        }
        __syncthreads();
#pragma unroll
        for (int kk = 0; kk < BK; kk++) {
            float a0 = hs[kk][ry * 4 + 0];
            float a1 = hs[kk][ry * 4 + 1];
            float a2 = hs[kk][ry * 4 + 2];
            float a3 = hs[kk][ry * 4 + 3];
            float4 wv = *(const float4*)&Ws[kk][cx * 4];
            acc[0][0] += a0 * wv.x; acc[0][1] += a0 * wv.y; acc[0][2] += a0 * wv.z; acc[0][3] += a0 * wv.w;
            acc[1][0] += a1 * wv.x; acc[1][1] += a1 * wv.y; acc[1][2] += a1 * wv.z; acc[1][3] += a1 * wv.w;
            acc[2][0] += a2 * wv.x; acc[2][1] += a2 * wv.y; acc[2][2] += a2 * wv.z; acc[2][3] += a2 * wv.w;
            acc[3][0] += a3 * wv.x; acc[3][1] += a3 * wv.y; acc[3][2] += a3 * wv.z; acc[3][3] += a3 * wv.w;
        }
        __syncthreads();
    }
#pragma unroll
    for (int i = 0; i < 4; i++) {
        int b = b0 + ry * 4 + i;
#pragma unroll
        for (int j = 0; j < 4; j++) {
            int c = c0 + cx * 4 + j;
            float v = acc[i][j] + bA[c];
            if ((c >> 7) == (c & 127)) v += 1.0f;  // + identity
            g_A[(size_t)b * (LAT * LAT) + c] = v;
        }
    }
}

// ---------------- kernel 3: B_mat = h @ W_B + b_B ----------------
__global__ void k_gemmB(const float* __restrict__ WB, const float* __restrict__ bB) {
    int b = blockIdx.x;
    int tid = threadIdx.x;
    __shared__ float hs[HID];
    hs[tid] = g_h[b * HID + tid];
    __syncthreads();
    for (int c = tid; c < LAT * CTRL; c += 256) {
        float acc = bB[c];
#pragma unroll 8
        for (int k = 0; k < HID; k++) acc += hs[k] * WB[k * (LAT * CTRL) + c];
        g_Bm[b * (LAT * CTRL) + c] = acc;
    }
}

// ---------------- kernel 4: the sequential scan ----------------
// One CTA per batch. A row i lives in thread i's registers (32x float32x4).
// z double-buffered in SMEM (broadcast reads). fma.rn.f32x2 halves FFMA count.
__global__ void __launch_bounds__(128, 3)
k_scan(const float* __restrict__ x_init, const float* __restrict__ Wenc,
       const float* __restrict__ benc, const float* __restrict__ u_future) {
    int b = blockIdx.x;
    int i = threadIdx.x;

    __shared__ float zs[2][LAT];
    __shared__ float xi[16];

    // A row -> registers as 32 packed pairs-of-pairs
    ulonglong2 a[32];
    const ulonglong2* Ab = (const ulonglong2*)(g_A + (size_t)b * (LAT * LAT) + (size_t)i * LAT);
#pragma unroll
    for (int t = 0; t < 32; t++) a[t] = Ab[t];

    float4 brow = ((const float4*)g_Bm)[b * LAT + i];

    if (i < STATE) xi[i] = x_init[b * STATE + i];
    __syncthreads();

    // z0 = x_init @ W_enc + b_enc
    float z0 = benc[i];
#pragma unroll
    for (int s = 0; s < STATE; s++) z0 += xi[s] * Wenc[s * LAT + i];
    zs[0][i] = z0;
    g_z[((size_t)b * (Tt + 1)) * LAT + i] = z0;
    __syncthreads();

    const float4* u4 = (const float4*)u_future + (size_t)b * Tt;
    float4 u = u4[0];
    int cur = 0;

    for (int k = 0; k < Tt; k++) {
        float4 unext = (k + 1 < Tt) ? u4[k + 1] : make_float4(0.f, 0.f, 0.f, 0.f);
        float ci = brow.x * u.x + brow.y * u.y + brow.z * u.z + brow.w * u.w;

        const ulonglong2* zv2 = (const ulonglong2*)zs[cur];
        unsigned long long acc01 = pack2(ci, 0.f);
        unsigned long long acc23 = pack2(0.f, 0.f);
#pragma unroll
        for (int t = 0; t < 32; t++) {
            ulonglong2 zv = zv2[t];
            ffma2(acc01, a[t].x, zv.x);
            ffma2(acc23, a[t].y, zv.y);
        }
        float s0, s1, s2, s3;
        unpack2(acc01, s0, s1);
        unpack2(acc23, s2, s3);
        float zn = (s0 + s2) + (s1 + s3);

        zs[cur ^ 1][i] = zn;
        g_z[((size_t)b * (Tt + 1) + k + 1) * LAT + i] = zn;
        u = unext;
        __syncthreads();
        cur ^= 1;
    }
}

// ---------------- kernel 5: decode + slice normalization ----------------
// warp-per-row: out[row] = z[row] @ W_dec + b_dec; normalize cols [3,7)
__global__ void k_dec(const float* __restrict__ Wdec, const float* __restrict__ bdec,
                      float* __restrict__ out) {
    __shared__ float Wt[STATE * LAT];  // transposed: Wt[o*128 + c]
    __shared__ float bs[STATE];
    int tid = threadIdx.x;
    for (int idx = tid; idx < STATE * LAT; idx += 256) {
        int o = idx >> 7, c = idx & 127;
        Wt[idx] = Wdec[c * STATE + o];
    }
    if (tid < STATE) bs[tid] = bdec[tid];
    __syncthreads();

    int warp = tid >> 5, lane = tid & 31;
    size_t row = (size_t)blockIdx.x * 8 + warp;
    if (row >= (size_t)Bn * (Tt + 1)) return;

    float4 zv = ((const float4*)g_z)[row * 32 + lane];

    float s[STATE];
#pragma unroll
    for (int o = 0; o < STATE; o++) {
        float4 wv = ((const float4*)Wt)[o * 32 + lane];
        float p = zv.x * wv.x + zv.y * wv.y + zv.z * wv.z + zv.w * wv.w;
        p += __shfl_xor_sync(0xFFFFFFFFu, p, 16);
        p += __shfl_xor_sync(0xFFFFFFFFu, p, 8);
        p += __shfl_xor_sync(0xFFFFFFFFu, p, 4);
        p += __shfl_xor_sync(0xFFFFFFFFu, p, 2);
        p += __shfl_xor_sync(0xFFFFFFFFu, p, 1);
        s[o] = p + bs[o];
    }
    float nrm = sqrtf(s[3] * s[3] + s[4] * s[4] + s[5] * s[5] + s[6] * s[6]);
    float inv = 1.0f / fmaxf(nrm, 1e-12f);
#pragma unroll
    for (int o = 0; o < STATE; o++) {
        float v = s[o];
        if (o >= 3 && o < 7) v *= inv;
        if (lane == o) out[row * STATE + o] = v;
    }
}

// ---------------- launcher ----------------
extern "C" void kernel_launch(void* const* d_in, const int* in_sizes, int n_in,
                              void* d_out, int out_size) {
    const float* x_history = (const float*)d_in[0];
    const float* u_history = (const float*)d_in[1];
    const float* x_init    = (const float*)d_in[2];
    // d_in[3] = x_future (unused by the reference computation)
    const float* u_future  = (const float*)d_in[4];
    // d_in[5] = n_steps (always Tt)
    const float* W_ctxt    = (const float*)d_in[6];
    const float* b_ctxt    = (const float*)d_in[7];
    const float* W_A       = (const float*)d_in[8];
    const float* b_A       = (const float*)d_in[9];
    const float* W_B       = (const float*)d_in[10];
    const float* b_B       = (const float*)d_in[11];
    const float* W_enc     = (const float*)d_in[12];
    const float* b_enc     = (const float*)d_in[13];
    const float* W_dec     = (const float*)d_in[14];
    const float* b_dec     = (const float*)d_in[15];
    float* out = (float*)d_out;

    k_ctxt<<<Bn, 256>>>(x_history, u_history, W_ctxt, b_ctxt);
    k_gemmA<<<dim3((LAT * LAT) / BN, Bn / BM), 256>>>(W_A, b_A);
    k_gemmB<<<Bn, 256>>>(W_B, b_B);
    k_scan<<<Bn, 128>>>(x_init, W_enc, b_enc, u_future);

    int rows = Bn * (Tt + 1);
    k_dec<<<(rows + 7) / 8, 256>>>(W_dec, b_dec, out);
}